// round 3
// baseline (speedup 1.0000x reference)
#include <cuda_runtime.h>
#include <math.h>

// Problem constants (B=2, S=1024, H=2048, I=1408, E=8, TOP_K=2)
#define T_TOK 2048
#define H_DIM 2048
#define I_DIM 1408
#define E_NUM 8
#define GU_W  (2*I_DIM)   // 2816

// ---------------- scratch (device globals; no allocations allowed) ----------
__device__ int   g_counts[E_NUM];
__device__ int   g_tok [E_NUM*T_TOK];
__device__ float g_wgt [E_NUM*T_TOK];
__device__ int   g_slot[E_NUM*T_TOK];
__device__ __align__(16) float g_gu[(size_t)E_NUM*T_TOK*GU_W];        // ~184 MB
__device__ __align__(16) float g_slotout[2ull*T_TOK*H_DIM];           // ~33 MB

// ---------------- kernel 0: zero counters ----------------------------------
__global__ void zero_counts_kernel() {
    if (threadIdx.x < E_NUM) g_counts[threadIdx.x] = 0;
}

// ---------------- kernel 1: gating (logits -> softmax -> top2 -> scatter) ---
__global__ void gate_kernel(const float* __restrict__ x,
                            const float* __restrict__ gw) {
    const int t = blockIdx.x;
    const float* xr = x + (size_t)t * H_DIM;

    float acc[E_NUM];
#pragma unroll
    for (int e = 0; e < E_NUM; e++) acc[e] = 0.f;

    for (int h = threadIdx.x; h < H_DIM; h += blockDim.x) {
        float xv = xr[h];
#pragma unroll
        for (int e = 0; e < E_NUM; e++)
            acc[e] += xv * gw[e * H_DIM + h];
    }

    // warp reduce, then cross-warp via smem
    __shared__ float s_part[E_NUM][8];
    __shared__ float s_logit[E_NUM];
    const int lane = threadIdx.x & 31;
    const int warp = threadIdx.x >> 5;
#pragma unroll
    for (int off = 16; off > 0; off >>= 1) {
#pragma unroll
        for (int e = 0; e < E_NUM; e++)
            acc[e] += __shfl_down_sync(0xffffffffu, acc[e], off);
    }
    if (lane == 0) {
#pragma unroll
        for (int e = 0; e < E_NUM; e++) s_part[e][warp] = acc[e];
    }
    __syncthreads();
    if (threadIdx.x < E_NUM) {
        float s = 0.f;
#pragma unroll
        for (int w = 0; w < 8; w++) s += s_part[threadIdx.x][w];
        s_logit[threadIdx.x] = s;
    }
    __syncthreads();

    if (threadIdx.x == 0) {
        float lg[E_NUM];
#pragma unroll
        for (int e = 0; e < E_NUM; e++) lg[e] = s_logit[e];
        float mx = lg[0];
#pragma unroll
        for (int e = 1; e < E_NUM; e++) mx = fmaxf(mx, lg[e]);
        float pe[E_NUM]; float se = 0.f;
#pragma unroll
        for (int e = 0; e < E_NUM; e++) { pe[e] = expf(lg[e] - mx); se += pe[e]; }
#pragma unroll
        for (int e = 0; e < E_NUM; e++) pe[e] /= se;

        // top-2, lowest index wins on ties (matches jax.lax.top_k)
        int b0 = 0;
#pragma unroll
        for (int e = 1; e < E_NUM; e++) if (pe[e] > pe[b0]) b0 = e;
        int b1 = -1;
#pragma unroll
        for (int e = 0; e < E_NUM; e++)
            if (e != b0 && (b1 < 0 || pe[e] > pe[b1])) b1 = e;

        float s2 = pe[b0] + pe[b1];
        int p0 = atomicAdd(&g_counts[b0], 1);
        g_tok [b0 * T_TOK + p0] = t;
        g_wgt [b0 * T_TOK + p0] = pe[b0] / s2;
        g_slot[b0 * T_TOK + p0] = 0;
        int p1 = atomicAdd(&g_counts[b1], 1);
        g_tok [b1 * T_TOK + p1] = t;
        g_wgt [b1 * T_TOK + p1] = pe[b1] / s2;
        g_slot[b1 * T_TOK + p1] = 1;
    }
}

// ---------------- kernel 2: GEMM1  gu = x[tok] * w1[e]^T --------------------
// A: gathered token rows of x [rows, H]; B: w1[e] rows [2I, H] (both K-contig)
__global__ __launch_bounds__(256)
void gemm1_kernel(const float* __restrict__ x, const float* __restrict__ w1) {
    const int e    = blockIdx.z;
    const int rows = g_counts[e];
    const int m0   = blockIdx.x * 128;
    if (m0 >= rows) return;
    const int n0   = blockIdx.y * 128;

    __shared__ float As[8][128];
    __shared__ float Bs[8][128];

    const int tid   = threadIdx.x;
    const int ldrow = tid >> 1;        // 0..127
    const int ldk   = (tid & 1) * 4;   // 0 or 4

    const int  mrow    = m0 + ldrow;
    const bool a_valid = (mrow < rows);
    const float* aptr  = a_valid ? (x + (size_t)g_tok[e * T_TOK + mrow] * H_DIM) : x;
    const float* bptr  = w1 + (size_t)e * GU_W * H_DIM + (size_t)(n0 + ldrow) * H_DIM;

    const int tx = tid & 15;   // 0..15 -> n
    const int ty = tid >> 4;   // 0..15 -> m

    float acc[8][8];
#pragma unroll
    for (int i = 0; i < 8; i++)
#pragma unroll
        for (int j = 0; j < 8; j++) acc[i][j] = 0.f;

    for (int k0 = 0; k0 < H_DIM; k0 += 8) {
        float4 a4 = a_valid ? *(const float4*)(aptr + k0 + ldk)
                            : make_float4(0.f, 0.f, 0.f, 0.f);
        float4 b4 = *(const float4*)(bptr + k0 + ldk);
        __syncthreads();
        As[ldk + 0][ldrow] = a4.x; As[ldk + 1][ldrow] = a4.y;
        As[ldk + 2][ldrow] = a4.z; As[ldk + 3][ldrow] = a4.w;
        Bs[ldk + 0][ldrow] = b4.x; Bs[ldk + 1][ldrow] = b4.y;
        Bs[ldk + 2][ldrow] = b4.z; Bs[ldk + 3][ldrow] = b4.w;
        __syncthreads();
#pragma unroll
        for (int k = 0; k < 8; k++) {
            float a[8], b[8];
            *(float4*)&a[0] = *(const float4*)&As[k][ty * 8];
            *(float4*)&a[4] = *(const float4*)&As[k][ty * 8 + 4];
            *(float4*)&b[0] = *(const float4*)&Bs[k][tx * 8];
            *(float4*)&b[4] = *(const float4*)&Bs[k][tx * 8 + 4];
#pragma unroll
            for (int i = 0; i < 8; i++)
#pragma unroll
                for (int j = 0; j < 8; j++) acc[i][j] += a[i] * b[j];
        }
    }

#pragma unroll
    for (int i = 0; i < 8; i++) {
        const int mi = m0 + ty * 8 + i;
        if (mi < rows) {
            float* dst = g_gu + (size_t)(e * T_TOK + mi) * GU_W + n0 + tx * 8;
            *(float4*)(dst)     = make_float4(acc[i][0], acc[i][1], acc[i][2], acc[i][3]);
            *(float4*)(dst + 4) = make_float4(acc[i][4], acc[i][5], acc[i][6], acc[i][7]);
        }
    }
}

// ---------------- kernel 3: act = silu(g) * u, in-place into gu[:, 0:I] -----
__global__ void act_kernel() {
    const int row = blockIdx.x;           // 0 .. E*T-1
    const int e   = row / T_TOK;
    const int pos = row % T_TOK;
    if (pos >= g_counts[e]) return;
    float* gu = g_gu + (size_t)row * GU_W;
    for (int i = threadIdx.x * 4; i < I_DIM; i += blockDim.x * 4) {
        float4 g4 = *(const float4*)(gu + i);
        float4 u4 = *(const float4*)(gu + I_DIM + i);
        float4 r;
        r.x = (g4.x / (1.f + expf(-g4.x))) * u4.x;
        r.y = (g4.y / (1.f + expf(-g4.y))) * u4.y;
        r.z = (g4.z / (1.f + expf(-g4.z))) * u4.z;
        r.w = (g4.w / (1.f + expf(-g4.w))) * u4.w;
        *(float4*)(gu + i) = r;
    }
}

// ---------------- kernel 4: GEMM2  slot_out = wgt * (act * w2[e]^T) ---------
__global__ __launch_bounds__(256)
void gemm2_kernel(const float* __restrict__ w2) {
    const int e    = blockIdx.z;
    const int rows = g_counts[e];
    const int m0   = blockIdx.x * 128;
    if (m0 >= rows) return;
    const int n0   = blockIdx.y * 128;

    __shared__ float As[8][128];
    __shared__ float Bs[8][128];

    const int tid   = threadIdx.x;
    const int ldrow = tid >> 1;
    const int ldk   = (tid & 1) * 4;

    const int  mrow    = m0 + ldrow;
    const bool a_valid = (mrow < rows);
    const float* aptr  = g_gu + (size_t)(e * T_TOK + (a_valid ? mrow : 0)) * GU_W;
    const float* bptr  = w2 + (size_t)e * H_DIM * I_DIM + (size_t)(n0 + ldrow) * I_DIM;

    const int tx = tid & 15;
    const int ty = tid >> 4;

    float acc[8][8];
#pragma unroll
    for (int i = 0; i < 8; i++)
#pragma unroll
        for (int j = 0; j < 8; j++) acc[i][j] = 0.f;

    for (int k0 = 0; k0 < I_DIM; k0 += 8) {
        float4 a4 = a_valid ? *(const float4*)(aptr + k0 + ldk)
                            : make_float4(0.f, 0.f, 0.f, 0.f);
        float4 b4 = *(const float4*)(bptr + k0 + ldk);
        __syncthreads();
        As[ldk + 0][ldrow] = a4.x; As[ldk + 1][ldrow] = a4.y;
        As[ldk + 2][ldrow] = a4.z; As[ldk + 3][ldrow] = a4.w;
        Bs[ldk + 0][ldrow] = b4.x; Bs[ldk + 1][ldrow] = b4.y;
        Bs[ldk + 2][ldrow] = b4.z; Bs[ldk + 3][ldrow] = b4.w;
        __syncthreads();
#pragma unroll
        for (int k = 0; k < 8; k++) {
            float a[8], b[8];
            *(float4*)&a[0] = *(const float4*)&As[k][ty * 8];
            *(float4*)&a[4] = *(const float4*)&As[k][ty * 8 + 4];
            *(float4*)&b[0] = *(const float4*)&Bs[k][tx * 8];
            *(float4*)&b[4] = *(const float4*)&Bs[k][tx * 8 + 4];
#pragma unroll
            for (int i = 0; i < 8; i++)
#pragma unroll
                for (int j = 0; j < 8; j++) acc[i][j] += a[i] * b[j];
        }
    }

#pragma unroll
    for (int i = 0; i < 8; i++) {
        const int mi = m0 + ty * 8 + i;
        if (mi < rows) {
            const int   li   = e * T_TOK + mi;
            const float w    = g_wgt[li];
            const int   tok  = g_tok[li];
            const int   slot = g_slot[li];
            float* dst = g_slotout + (size_t)slot * T_TOK * H_DIM
                                   + (size_t)tok * H_DIM + n0 + tx * 8;
            *(float4*)(dst)     = make_float4(w*acc[i][0], w*acc[i][1], w*acc[i][2], w*acc[i][3]);
            *(float4*)(dst + 4) = make_float4(w*acc[i][4], w*acc[i][5], w*acc[i][6], w*acc[i][7]);
        }
    }
}

// ---------------- kernel 5: combine slot0 + slot1 -> out --------------------
__global__ void combine_kernel(float* __restrict__ out) {
    const size_t idx4 = (size_t)blockIdx.x * blockDim.x + threadIdx.x;
    const size_t n4   = (size_t)T_TOK * H_DIM / 4;
    if (idx4 >= n4) return;
    float4 a = *((const float4*)g_slotout + idx4);
    float4 b = *((const float4*)g_slotout + (size_t)T_TOK * H_DIM / 4 + idx4);
    float4 r; r.x = a.x + b.x; r.y = a.y + b.y; r.z = a.z + b.z; r.w = a.w + b.w;
    *((float4*)out + idx4) = r;
}

// ---------------- launch ----------------------------------------------------
extern "C" void kernel_launch(void* const* d_in, const int* in_sizes, int n_in,
                              void* d_out, int out_size) {
    const float* x  = (const float*)d_in[0];   // [2,1024,2048]
    const float* gw = (const float*)d_in[1];   // [8,2048]
    const float* w1 = (const float*)d_in[2];   // [8,2816,2048]
    const float* w2 = (const float*)d_in[3];   // [8,2048,1408]
    float* out = (float*)d_out;                // [2,1024,2048] fp32

    zero_counts_kernel<<<1, 32>>>();
    gate_kernel<<<T_TOK, 256>>>(x, gw);

    dim3 g1(T_TOK / 128, GU_W / 128, E_NUM);   // (16, 22, 8)
    gemm1_kernel<<<g1, 256>>>(x, w1);

    act_kernel<<<E_NUM * T_TOK, 128>>>();

    dim3 g2(T_TOK / 128, H_DIM / 128, E_NUM);  // (16, 16, 8)
    gemm2_kernel<<<g2, 256>>>(w2);

    combine_kernel<<<(T_TOK * H_DIM / 4 + 255) / 256, 256>>>(out);
}

// round 5
// speedup vs baseline: 1.5817x; 1.5817x over previous
#include <cuda_runtime.h>
#include <math.h>
#include <stdint.h>

// Problem constants (B=2, S=1024, H=2048, I=1408, E=8, TOP_K=2)
#define T_TOK 2048
#define H_DIM 2048
#define I_DIM 1408
#define E_NUM 8
#define GU_W  (2*I_DIM)   // 2816

// ---------------- scratch (device globals; no allocations allowed) ----------
__device__ int   g_counts[E_NUM];
__device__ int   g_tok [E_NUM*T_TOK];
__device__ float g_wgt [E_NUM*T_TOK];
__device__ int   g_slot[E_NUM*T_TOK];
__device__ __align__(16) float g_gu[(size_t)E_NUM*T_TOK*GU_W];        // ~184 MB
__device__ __align__(16) float g_slotout[2ull*T_TOK*H_DIM];           // ~33 MB

// ---------------- PTX helpers ----------------------------------------------
__device__ __forceinline__ uint32_t cvta_smem(const void* p) {
    uint32_t r;
    asm("{ .reg .u64 t; cvta.to.shared.u64 t, %1; cvt.u32.u64 %0, t; }"
        : "=r"(r) : "l"(p));
    return r;
}
__device__ __forceinline__ void ldsm4(uint32_t* r, uint32_t addr) {
    asm volatile("ldmatrix.sync.aligned.m8n8.x4.shared.b16 {%0,%1,%2,%3}, [%4];"
        : "=r"(r[0]), "=r"(r[1]), "=r"(r[2]), "=r"(r[3]) : "r"(addr));
}
__device__ __forceinline__ void mma_tf32(float* c, const uint32_t* a, const uint32_t* b) {
    asm volatile(
        "mma.sync.aligned.m16n8k8.row.col.f32.tf32.tf32.f32 "
        "{%0,%1,%2,%3}, {%4,%5,%6,%7}, {%8,%9}, {%0,%1,%2,%3};"
        : "+f"(c[0]), "+f"(c[1]), "+f"(c[2]), "+f"(c[3])
        : "r"(a[0]), "r"(a[1]), "r"(a[2]), "r"(a[3]), "r"(b[0]), "r"(b[1]));
}
// 3xTF32 operand split: v = hi + lo, hi = tf32_rna(v), lo = tf32_rna(v - hi)
__device__ __forceinline__ void split_tf32(uint32_t raw, uint32_t& hi, uint32_t& lo) {
    float v = __uint_as_float(raw);
    asm("cvt.rna.tf32.f32 %0, %1;" : "=r"(hi) : "f"(v));
    float l = v - __uint_as_float(hi);
    asm("cvt.rna.tf32.f32 %0, %1;" : "=r"(lo) : "f"(l));
}
__device__ __forceinline__ void cp16(uint32_t dst, const void* src, int src_bytes) {
    asm volatile("cp.async.ca.shared.global [%0], [%1], 16, %2;"
        :: "r"(dst), "l"(src), "r"(src_bytes));
}
__device__ __forceinline__ void cp_commit() { asm volatile("cp.async.commit_group;"); }
__device__ __forceinline__ void cp_wait1()  { asm volatile("cp.async.wait_group 1;"); }
__device__ __forceinline__ void cp_wait0()  { asm volatile("cp.async.wait_group 0;"); }

// smem layout per stage: A tile 128x32 fp32 (16KB) + B tile 128x32 (16KB).
// Row = 128 bytes (8 chunks of 16B); chunk index swizzled: c ^= (row & 7).
#define STG_BYTES 32768
#define A_OFF(buf) ((buf) * STG_BYTES)
#define B_OFF(buf) ((buf) * STG_BYTES + 16384)

// ---------------- kernel 0: zero counters ----------------------------------
__global__ void zero_counts_kernel() {
    if (threadIdx.x < E_NUM) g_counts[threadIdx.x] = 0;
}

// ---------------- kernel 1: gating ------------------------------------------
__global__ void gate_kernel(const float* __restrict__ x,
                            const float* __restrict__ gw) {
    const int t = blockIdx.x;
    const float* xr = x + (size_t)t * H_DIM;

    float acc[E_NUM];
#pragma unroll
    for (int e = 0; e < E_NUM; e++) acc[e] = 0.f;
    for (int h = threadIdx.x; h < H_DIM; h += blockDim.x) {
        float xv = xr[h];
#pragma unroll
        for (int e = 0; e < E_NUM; e++) acc[e] += xv * gw[e * H_DIM + h];
    }
    __shared__ float s_part[E_NUM][8];
    __shared__ float s_logit[E_NUM];
    const int lane = threadIdx.x & 31, warp = threadIdx.x >> 5;
#pragma unroll
    for (int off = 16; off > 0; off >>= 1)
#pragma unroll
        for (int e = 0; e < E_NUM; e++)
            acc[e] += __shfl_down_sync(0xffffffffu, acc[e], off);
    if (lane == 0)
#pragma unroll
        for (int e = 0; e < E_NUM; e++) s_part[e][warp] = acc[e];
    __syncthreads();
    if (threadIdx.x < E_NUM) {
        float s = 0.f;
#pragma unroll
        for (int w = 0; w < 8; w++) s += s_part[threadIdx.x][w];
        s_logit[threadIdx.x] = s;
    }
    __syncthreads();
    if (threadIdx.x == 0) {
        float lg[E_NUM];
#pragma unroll
        for (int e = 0; e < E_NUM; e++) lg[e] = s_logit[e];
        float mx = lg[0];
#pragma unroll
        for (int e = 1; e < E_NUM; e++) mx = fmaxf(mx, lg[e]);
        float pe[E_NUM], se = 0.f;
#pragma unroll
        for (int e = 0; e < E_NUM; e++) { pe[e] = expf(lg[e] - mx); se += pe[e]; }
#pragma unroll
        for (int e = 0; e < E_NUM; e++) pe[e] /= se;
        int b0 = 0;
#pragma unroll
        for (int e = 1; e < E_NUM; e++) if (pe[e] > pe[b0]) b0 = e;
        int b1 = -1;
#pragma unroll
        for (int e = 0; e < E_NUM; e++)
            if (e != b0 && (b1 < 0 || pe[e] > pe[b1])) b1 = e;
        float s2 = pe[b0] + pe[b1];
        int p0 = atomicAdd(&g_counts[b0], 1);
        g_tok [b0 * T_TOK + p0] = t; g_wgt[b0 * T_TOK + p0] = pe[b0] / s2;
        g_slot[b0 * T_TOK + p0] = 0;
        int p1 = atomicAdd(&g_counts[b1], 1);
        g_tok [b1 * T_TOK + p1] = t; g_wgt[b1 * T_TOK + p1] = pe[b1] / s2;
        g_slot[b1 * T_TOK + p1] = 1;
    }
}

// ---- shared 3xTF32 MMA core for one k-slab (4 substeps of k=8) -------------
// af/bf are loaded, split into hi/lo, and 3 MMAs per pair are issued.
#define MMA_KSLAB(Ab, Bb)                                                      \
    do {                                                                       \
        _Pragma("unroll")                                                      \
        for (int s = 0; s < 4; s++) {                                          \
            uint32_t afh[4][4], afl[4][4], bfh[4][2], bfl[4][2];               \
            _Pragma("unroll")                                                  \
            for (int mt = 0; mt < 4; mt++) {                                   \
                uint32_t raw[4];                                               \
                ldsm4(raw, (Ab) + aRow[mt] * 128 +                             \
                           (((2 * s + agsel) ^ (aRow[mt] & 7)) << 4));         \
                _Pragma("unroll")                                              \
                for (int q = 0; q < 4; q++)                                    \
                    split_tf32(raw[q], afh[mt][q], afl[mt][q]);                \
            }                                                                  \
            _Pragma("unroll")                                                  \
            for (int p = 0; p < 2; p++) {                                      \
                uint32_t r[4];                                                 \
                ldsm4(r, (Bb) + bRow[p] * 128 +                                \
                         (((2 * s + bgsel) ^ (bRow[p] & 7)) << 4));            \
                split_tf32(r[0], bfh[2*p][0],   bfl[2*p][0]);                  \
                split_tf32(r[1], bfh[2*p][1],   bfl[2*p][1]);                  \
                split_tf32(r[2], bfh[2*p+1][0], bfl[2*p+1][0]);                \
                split_tf32(r[3], bfh[2*p+1][1], bfl[2*p+1][1]);                \
            }                                                                  \
            _Pragma("unroll")                                                  \
            for (int mt = 0; mt < 4; mt++)                                     \
                _Pragma("unroll")                                              \
                for (int nt = 0; nt < 4; nt++) {                               \
                    mma_tf32(acc[mt][nt], afh[mt], bfl[nt]);                   \
                    mma_tf32(acc[mt][nt], afl[mt], bfh[nt]);                   \
                    mma_tf32(acc[mt][nt], afh[mt], bfh[nt]);                   \
                }                                                              \
        }                                                                      \
    } while (0)

// ---------------- 3xTF32 GEMM1: gu[rows, 2I] = x[tok] * w1[e]^T -------------
// CTA 128x128x32, 8 warps (2m x 4n), warp tile 64x32, mma m16n8k8 tf32.
__global__ __launch_bounds__(256, 1)
void gemm1_kernel(const float* __restrict__ x, const float* __restrict__ w1) {
    const int e    = blockIdx.z;
    const int rows = g_counts[e];
    const int m0   = blockIdx.x * 128;
    if (m0 >= rows) return;
    const int n0   = blockIdx.y * 128;

    extern __shared__ __align__(16) char smem[];
    const uint32_t sb = cvta_smem(smem);

    const int tid  = threadIdx.x;
    const int lane = tid & 31;
    const int wid  = tid >> 5;
    const int wm   = wid & 1;       // 0..1
    const int wn   = wid >> 1;      // 0..3

    const int ca = tid & 7;                 // chunk within row
    const float* asrc[4];
    int          apred[4];
    const float* bsrc[4];
    uint32_t     sdst[4];
#pragma unroll
    for (int i = 0; i < 4; i++) {
        int r = (tid >> 3) + 32 * i;        // 0..127
        int mi = m0 + r;
        int valid = (mi < rows);
        int tok = valid ? g_tok[e * T_TOK + mi] : 0;
        asrc[i]  = x + (size_t)tok * H_DIM + ca * 4;
        apred[i] = valid ? 16 : 0;
        bsrc[i]  = w1 + (size_t)e * GU_W * H_DIM + (size_t)(n0 + r) * H_DIM + ca * 4;
        sdst[i]  = (uint32_t)(r * 128 + ((ca ^ (r & 7)) << 4));
    }

    const int grp = lane >> 3, r8 = lane & 7;
    const int agsel = grp >> 1;
    const int bgsel = grp & 1;
    int aRow[4], bRow[2];
#pragma unroll
    for (int mt = 0; mt < 4; mt++) aRow[mt] = wm * 64 + mt * 16 + ((grp & 1) << 3) + r8;
#pragma unroll
    for (int p = 0; p < 2; p++)    bRow[p]  = wn * 32 + p * 16 + ((grp >> 1) << 3) + r8;

    float acc[4][4][4];
#pragma unroll
    for (int i = 0; i < 4; i++)
#pragma unroll
        for (int j = 0; j < 4; j++)
#pragma unroll
            for (int k = 0; k < 4; k++) acc[i][j][k] = 0.f;

    const int KT = H_DIM / 32;   // 64

#pragma unroll
    for (int i = 0; i < 4; i++) {
        cp16(sb + A_OFF(0) + sdst[i], asrc[i], apred[i]);
        cp16(sb + B_OFF(0) + sdst[i], bsrc[i], 16);
    }
    cp_commit();

    for (int kt = 0; kt < KT; kt++) {
        const int buf = kt & 1;
        if (kt + 1 < KT) {
            const int nb = (kt + 1) & 1;
            const int ko = (kt + 1) * 32;
#pragma unroll
            for (int i = 0; i < 4; i++) {
                cp16(sb + A_OFF(nb) + sdst[i], asrc[i] + ko, apred[i]);
                cp16(sb + B_OFF(nb) + sdst[i], bsrc[i] + ko, 16);
            }
            cp_commit();
            cp_wait1();
        } else {
            cp_wait0();
        }
        __syncthreads();

        const uint32_t Ab = sb + A_OFF(buf);
        const uint32_t Bb = sb + B_OFF(buf);
        MMA_KSLAB(Ab, Bb);
        __syncthreads();
    }

    const int lr = lane >> 2, lc = (lane & 3) * 2;
    const int mb = m0 + wm * 64, nb = n0 + wn * 32;
#pragma unroll
    for (int mt = 0; mt < 4; mt++) {
#pragma unroll
        for (int half = 0; half < 2; half++) {
            const int row = mb + mt * 16 + half * 8 + lr;
            if (row < rows) {
                float* dst = g_gu + (size_t)(e * T_TOK + row) * GU_W + nb + lc;
#pragma unroll
                for (int nt = 0; nt < 4; nt++) {
                    float2 v = make_float2(acc[mt][nt][2 * half], acc[mt][nt][2 * half + 1]);
                    *(float2*)(dst + nt * 8) = v;
                }
            }
        }
    }
}

// ---------------- kernel 3: act = silu(g) * u (in place) --------------------
__global__ void act_kernel() {
    const int row = blockIdx.x;
    const int e   = row / T_TOK;
    const int pos = row % T_TOK;
    if (pos >= g_counts[e]) return;
    float* gu = g_gu + (size_t)row * GU_W;
    for (int i = threadIdx.x * 4; i < I_DIM; i += blockDim.x * 4) {
        float4 g4 = *(const float4*)(gu + i);
        float4 u4 = *(const float4*)(gu + I_DIM + i);
        float4 r;
        r.x = (g4.x / (1.f + expf(-g4.x))) * u4.x;
        r.y = (g4.y / (1.f + expf(-g4.y))) * u4.y;
        r.z = (g4.z / (1.f + expf(-g4.z))) * u4.z;
        r.w = (g4.w / (1.f + expf(-g4.w))) * u4.w;
        *(float4*)(gu + i) = r;
    }
}

// ---------------- 3xTF32 GEMM2: slot_out = wgt * (act * w2[e]^T) ------------
__global__ __launch_bounds__(256, 1)
void gemm2_kernel(const float* __restrict__ w2) {
    const int e    = blockIdx.z;
    const int rows = g_counts[e];
    const int m0   = blockIdx.x * 128;
    if (m0 >= rows) return;
    const int n0   = blockIdx.y * 128;

    extern __shared__ __align__(16) char smem[];
    const uint32_t sb = cvta_smem(smem);

    const int tid  = threadIdx.x;
    const int lane = tid & 31;
    const int wid  = tid >> 5;
    const int wm   = wid & 1;
    const int wn   = wid >> 1;

    const int ca = tid & 7;
    const float* asrc[4];
    int          apred[4];
    const float* bsrc[4];
    uint32_t     sdst[4];
#pragma unroll
    for (int i = 0; i < 4; i++) {
        int r = (tid >> 3) + 32 * i;
        int mi = m0 + r;
        int valid = (mi < rows);
        asrc[i]  = g_gu + (size_t)(e * T_TOK + (valid ? mi : 0)) * GU_W + ca * 4;
        apred[i] = valid ? 16 : 0;
        bsrc[i]  = w2 + (size_t)e * H_DIM * I_DIM + (size_t)(n0 + r) * I_DIM + ca * 4;
        sdst[i]  = (uint32_t)(r * 128 + ((ca ^ (r & 7)) << 4));
    }

    const int grp = lane >> 3, r8 = lane & 7;
    const int agsel = grp >> 1, bgsel = grp & 1;
    int aRow[4], bRow[2];
#pragma unroll
    for (int mt = 0; mt < 4; mt++) aRow[mt] = wm * 64 + mt * 16 + ((grp & 1) << 3) + r8;
#pragma unroll
    for (int p = 0; p < 2; p++)    bRow[p]  = wn * 32 + p * 16 + ((grp >> 1) << 3) + r8;

    float acc[4][4][4];
#pragma unroll
    for (int i = 0; i < 4; i++)
#pragma unroll
        for (int j = 0; j < 4; j++)
#pragma unroll
            for (int k = 0; k < 4; k++) acc[i][j][k] = 0.f;

    const int KT = I_DIM / 32;   // 44

#pragma unroll
    for (int i = 0; i < 4; i++) {
        cp16(sb + A_OFF(0) + sdst[i], asrc[i], apred[i]);
        cp16(sb + B_OFF(0) + sdst[i], bsrc[i], 16);
    }
    cp_commit();

    for (int kt = 0; kt < KT; kt++) {
        const int buf = kt & 1;
        if (kt + 1 < KT) {
            const int nbuf = (kt + 1) & 1;
            const int ko = (kt + 1) * 32;
#pragma unroll
            for (int i = 0; i < 4; i++) {
                cp16(sb + A_OFF(nbuf) + sdst[i], asrc[i] + ko, apred[i]);
                cp16(sb + B_OFF(nbuf) + sdst[i], bsrc[i] + ko, 16);
            }
            cp_commit();
            cp_wait1();
        } else {
            cp_wait0();
        }
        __syncthreads();

        const uint32_t Ab = sb + A_OFF(buf);
        const uint32_t Bb = sb + B_OFF(buf);
        MMA_KSLAB(Ab, Bb);
        __syncthreads();
    }

    const int lr = lane >> 2, lc = (lane & 3) * 2;
    const int mb = m0 + wm * 64, nbase = n0 + wn * 32;
#pragma unroll
    for (int mt = 0; mt < 4; mt++) {
#pragma unroll
        for (int half = 0; half < 2; half++) {
            const int row = mb + mt * 16 + half * 8 + lr;
            if (row < rows) {
                const int li = e * T_TOK + row;
                const float w = g_wgt[li];
                const int tok = g_tok[li];
                const int slot = g_slot[li];
                float* dst = g_slotout + (size_t)slot * T_TOK * H_DIM
                                       + (size_t)tok * H_DIM + nbase + lc;
#pragma unroll
                for (int nt = 0; nt < 4; nt++) {
                    float2 v = make_float2(w * acc[mt][nt][2 * half],
                                           w * acc[mt][nt][2 * half + 1]);
                    *(float2*)(dst + nt * 8) = v;
                }
            }
        }
    }
}

// ---------------- kernel 5: combine slot0 + slot1 -> out --------------------
__global__ void combine_kernel(float* __restrict__ out) {
    const size_t idx4 = (size_t)blockIdx.x * blockDim.x + threadIdx.x;
    const size_t n4   = (size_t)T_TOK * H_DIM / 4;
    if (idx4 >= n4) return;
    float4 a = *((const float4*)g_slotout + idx4);
    float4 b = *((const float4*)g_slotout + n4 + idx4);
    float4 r; r.x = a.x + b.x; r.y = a.y + b.y; r.z = a.z + b.z; r.w = a.w + b.w;
    *((float4*)out + idx4) = r;
}

// ---------------- launch ----------------------------------------------------
extern "C" void kernel_launch(void* const* d_in, const int* in_sizes, int n_in,
                              void* d_out, int out_size) {
    const float* x  = (const float*)d_in[0];
    const float* gw = (const float*)d_in[1];
    const float* w1 = (const float*)d_in[2];
    const float* w2 = (const float*)d_in[3];
    float* out = (float*)d_out;

    const int smem_bytes = 2 * STG_BYTES;   // 64 KB
    cudaFuncSetAttribute(gemm1_kernel, cudaFuncAttributeMaxDynamicSharedMemorySize, smem_bytes);
    cudaFuncSetAttribute(gemm2_kernel, cudaFuncAttributeMaxDynamicSharedMemorySize, smem_bytes);

    zero_counts_kernel<<<1, 32>>>();
    gate_kernel<<<T_TOK, 256>>>(x, gw);

    dim3 g1(T_TOK / 128, GU_W / 128, E_NUM);   // (16, 22, 8)
    gemm1_kernel<<<g1, 256, smem_bytes>>>(x, w1);

    act_kernel<<<E_NUM * T_TOK, 128>>>();

    dim3 g2(T_TOK / 128, H_DIM / 128, E_NUM);  // (16, 16, 8)
    gemm2_kernel<<<g2, 256, smem_bytes>>>(w2);

    combine_kernel<<<(T_TOK * H_DIM / 4 + 255) / 256, 256>>>(out);
}